// round 2
// baseline (speedup 1.0000x reference)
#include <cuda_runtime.h>

#define B_ 2
#define H_ 16
#define S_ 2048
#define D_ 64
#define TQ 64
#define TK 64
#define P_ 68            // padded smem row stride (multiple of 4 for LDS.128)
#define NBH (B_ * H_)

// per-row 1/sum(exp) — scratch for the normalization pass
__device__ float g_inv[NBH * S_];

// ---------------------------------------------------------------------------
// Pass 1: per (bh, q-tile of 64 rows):
//   - stream K/V in 64-wide tiles through smem
//   - scores = Q K^T / 8, e = exp(score)  (no max-subtraction: |s| <= ~6.2)
//   - write unnormalized e to attn buffer, accumulate unnormalized AV in regs
//   - epilogue: reduce rowsums, write 1/sum to g_inv, write result = AV/sum
// ---------------------------------------------------------------------------
__global__ __launch_bounds__(256) void attn_pass1(
    const float* __restrict__ q, const float* __restrict__ k,
    const float* __restrict__ v, float* __restrict__ out,
    float* __restrict__ attn)
{
    extern __shared__ float sm[];
    float* Qs = sm;               // [D_][P_]  transposed: Qs[d*P_ + row]
    float* Ks = sm + D_ * P_;     // [D_][P_]  transposed: Ks[d*P_ + col]
    float* Vs = sm + 2 * D_ * P_; // [TK][P_]  row-major:  Vs[kk*P_ + dv]
    float* Es = sm + 3 * D_ * P_; // [TK][P_]  transposed: Es[col*P_ + row]

    const int tid = threadIdx.x;
    const int tx = tid & 15;      // 0..15  -> 4 cols / 4 dv
    const int ty = tid >> 4;      // 0..15  -> 4 rows
    const int bh = blockIdx.y;
    const int qrow0 = blockIdx.x * TQ;
    const size_t base = (size_t)bh * S_ * D_;

    // ---- load Q tile transposed into smem ----
    for (int t = tid; t < TQ * D_ / 4; t += 256) {
        int r = t >> 4;           // q row within tile
        int g = (t & 15) << 2;    // d group
        float4 x = *(const float4*)(q + base + (size_t)(qrow0 + r) * D_ + g);
        Qs[(g + 0) * P_ + r] = x.x;
        Qs[(g + 1) * P_ + r] = x.y;
        Qs[(g + 2) * P_ + r] = x.z;
        Qs[(g + 3) * P_ + r] = x.w;
    }

    float acc_o[4][4];
    #pragma unroll
    for (int i = 0; i < 4; i++)
        #pragma unroll
        for (int j = 0; j < 4; j++) acc_o[i][j] = 0.f;
    float rs[4] = {0.f, 0.f, 0.f, 0.f};

    for (int kt = 0; kt < S_ / TK; kt++) {
        __syncthreads();   // prev iteration fully done with Ks/Vs/Es

        // ---- load K (transposed) and V (row-major) tiles ----
        for (int t = tid; t < TK * D_ / 4; t += 256) {
            int r = t >> 4;
            int g = (t & 15) << 2;
            size_t goff = base + (size_t)(kt * TK + r) * D_ + g;
            float4 x = *(const float4*)(k + goff);
            Ks[(g + 0) * P_ + r] = x.x;
            Ks[(g + 1) * P_ + r] = x.y;
            Ks[(g + 2) * P_ + r] = x.z;
            Ks[(g + 3) * P_ + r] = x.w;
            float4 y = *(const float4*)(v + goff);
            *(float4*)(Vs + r * P_ + g) = y;
        }
        __syncthreads();

        // ---- QK^T: 4x4 register block per thread ----
        float acc[4][4];
        #pragma unroll
        for (int i = 0; i < 4; i++)
            #pragma unroll
            for (int j = 0; j < 4; j++) acc[i][j] = 0.f;

        #pragma unroll 8
        for (int d = 0; d < D_; d++) {
            float4 a4 = *(const float4*)(Qs + d * P_ + 4 * ty);
            float4 b4 = *(const float4*)(Ks + d * P_ + 4 * tx);
            float av[4] = {a4.x, a4.y, a4.z, a4.w};
            float bv[4] = {b4.x, b4.y, b4.z, b4.w};
            #pragma unroll
            for (int i = 0; i < 4; i++)
                #pragma unroll
                for (int j = 0; j < 4; j++)
                    acc[i][j] = fmaf(av[i], bv[j], acc[i][j]);
        }

        // ---- e = exp(s/8); rowsum; write unnormalized attn ----
        float e[4][4];
        #pragma unroll
        for (int i = 0; i < 4; i++) {
            #pragma unroll
            for (int j = 0; j < 4; j++) {
                e[i][j] = __expf(acc[i][j] * 0.125f);
                rs[i] += e[i][j];
            }
            float4 w = make_float4(e[i][0], e[i][1], e[i][2], e[i][3]);
            *(float4*)(attn + ((size_t)(bh * S_ + qrow0 + 4 * ty + i)) * S_
                            + kt * TK + 4 * tx) = w;
        }

        // ---- stage e transposed for the AV gemm ----
        #pragma unroll
        for (int j = 0; j < 4; j++) {
            float4 c = make_float4(e[0][j], e[1][j], e[2][j], e[3][j]);
            *(float4*)(Es + (4 * tx + j) * P_ + 4 * ty) = c;
        }
        __syncthreads();

        // ---- AV: out[row][dv] += e[row][kk] * V[kk][dv] ----
        #pragma unroll 8
        for (int kk = 0; kk < TK; kk++) {
            float4 a4 = *(const float4*)(Es + kk * P_ + 4 * ty);
            float4 b4 = *(const float4*)(Vs + kk * P_ + 4 * tx);
            float av[4] = {a4.x, a4.y, a4.z, a4.w};
            float bv[4] = {b4.x, b4.y, b4.z, b4.w};
            #pragma unroll
            for (int i = 0; i < 4; i++)
                #pragma unroll
                for (int j = 0; j < 4; j++)
                    acc_o[i][j] = fmaf(av[i], bv[j], acc_o[i][j]);
        }
    }

    // ---- rowsum reduction across the 16 tx lanes ----
    __syncthreads();
    float* red  = Ks;          // reuse: 64 rows x 16 partials
    float* rinv = Ks + 1024;   // 64 inverses
    #pragma unroll
    for (int i = 0; i < 4; i++) red[(4 * ty + i) * 16 + tx] = rs[i];
    __syncthreads();
    if (tid < TQ) {
        float s = 0.f;
        #pragma unroll
        for (int t = 0; t < 16; t++) s += red[tid * 16 + t];
        float inv = 1.0f / s;
        rinv[tid] = inv;
        g_inv[bh * S_ + qrow0 + tid] = inv;
    }
    __syncthreads();

    // ---- write result = AV / rowsum ----
    #pragma unroll
    for (int i = 0; i < 4; i++) {
        float inv = rinv[4 * ty + i];
        float4 w = make_float4(acc_o[i][0] * inv, acc_o[i][1] * inv,
                               acc_o[i][2] * inv, acc_o[i][3] * inv);
        *(float4*)(out + ((size_t)(bh * S_ + qrow0 + 4 * ty + i)) * D_
                       + 4 * tx) = w;
    }
}

// ---------------------------------------------------------------------------
// Pass 2: attn[row][:] *= 1/rowsum   (pure streaming rescale, float4)
// ---------------------------------------------------------------------------
__global__ __launch_bounds__(256) void attn_norm(float* __restrict__ attn)
{
    const int row = blockIdx.x;                 // 0 .. NBH*S_-1
    const float inv = g_inv[row];
    float4* p = (float4*)(attn + (size_t)row * S_);
    const int t = threadIdx.x;
    float4 a = p[t];
    a.x *= inv; a.y *= inv; a.z *= inv; a.w *= inv;
    p[t] = a;
    float4 b = p[t + 256];
    b.x *= inv; b.y *= inv; b.z *= inv; b.w *= inv;
    p[t + 256] = b;
}

extern "C" void kernel_launch(void* const* d_in, const int* in_sizes, int n_in,
                              void* d_out, int out_size)
{
    const float* q = (const float*)d_in[0];
    const float* k = (const float*)d_in[1];
    const float* v = (const float*)d_in[2];
    float* out  = (float*)d_out;                       // [B,H,S,D]
    float* attn = out + (size_t)NBH * S_ * D_;         // [B,H,S,S]

    const int smem = 4 * D_ * P_ * sizeof(float);      // 69632 B
    cudaFuncSetAttribute(attn_pass1,
                         cudaFuncAttributeMaxDynamicSharedMemorySize, smem);

    dim3 g1(S_ / TQ, NBH);
    attn_pass1<<<g1, 256, smem>>>(q, k, v, out, attn);
    attn_norm<<<NBH * S_, 256>>>(attn);
}

// round 4
// speedup vs baseline: 1.3512x; 1.3512x over previous
#include <cuda_runtime.h>
#include <cuda_bf16.h>
#include <cstdint>

#define S_  2048
#define D_  64
#define NBH 32
#define TQ  128
#define TK  128
#define NKT (S_/TK)
#define P72 72      // padded row stride (bf16) for Q/K tiles: 144B -> 4-bank rotation
#define PV  136     // padded row stride (bf16) for V^T tiles: 272B -> 4-bank rotation

// ---- smem byte offsets ----
#define OQH 0
#define OQL (OQH + TQ*P72*2)
#define OKH (OQL + TQ*P72*2)
#define OKL (OKH + TK*P72*2)
#define OVH (OKL + TK*P72*2)
#define OVL (OVH + D_*PV*2)
#define ORED (OVL + D_*PV*2)
#define OINV (ORED + 128*4)
#define SMEM_BYTES (OINV + 128*4)   // 109568

__device__ __forceinline__ uint32_t smem_u32(const void* p) {
    uint32_t a;
    asm("{ .reg .u64 t; cvta.to.shared.u64 t, %1; cvt.u32.u64 %0, t; }"
        : "=r"(a) : "l"(p));
    return a;
}
__device__ __forceinline__ void ldsm4(uint32_t a, uint32_t r[4]) {
    asm volatile("ldmatrix.sync.aligned.m8n8.x4.shared.b16 {%0,%1,%2,%3}, [%4];"
        : "=r"(r[0]), "=r"(r[1]), "=r"(r[2]), "=r"(r[3]) : "r"(a));
}
__device__ __forceinline__ void ldsm2(uint32_t a, uint32_t r[2]) {
    asm volatile("ldmatrix.sync.aligned.m8n8.x2.shared.b16 {%0,%1}, [%2];"
        : "=r"(r[0]), "=r"(r[1]) : "r"(a));
}
__device__ __forceinline__ void mma16816(float c[4], const uint32_t a[4],
                                         const uint32_t b[2]) {
    asm volatile("mma.sync.aligned.m16n8k16.row.col.f32.bf16.bf16.f32 "
        "{%0,%1,%2,%3}, {%4,%5,%6,%7}, {%8,%9}, {%0,%1,%2,%3};"
        : "+f"(c[0]), "+f"(c[1]), "+f"(c[2]), "+f"(c[3])
        : "r"(a[0]), "r"(a[1]), "r"(a[2]), "r"(a[3]), "r"(b[0]), "r"(b[1]));
}
// split (x,y) into packed bf16x2 hi + bf16x2 lo (x in low half)
__device__ __forceinline__ void split2(float x, float y, uint32_t& h, uint32_t& l) {
    __nv_bfloat162 hb = __floats2bfloat162_rn(x, y);
    float lx = x - __bfloat162float(hb.x);
    float ly = y - __bfloat162float(hb.y);
    __nv_bfloat162 lb = __floats2bfloat162_rn(lx, ly);
    h = *(uint32_t*)&hb;
    l = *(uint32_t*)&lb;
}

// 128x64 fp32 gmem -> hi/lo bf16 row-major padded tiles
__device__ __forceinline__ void load_rm(char* sm, int offH, int offL,
                                        const float* g, float scale, int tid) {
    for (int t = tid; t < 128 * 16; t += 256) {
        int r = t >> 4, c = (t & 15) << 2;
        float4 x = *(const float4*)(g + (size_t)r * D_ + c);
        x.x *= scale; x.y *= scale; x.z *= scale; x.w *= scale;
        uint32_t h0, l0, h1, l1;
        split2(x.x, x.y, h0, l0);
        split2(x.z, x.w, h1, l1);
        uint32_t* H = (uint32_t*)(sm + offH + (size_t)(r * P72 + c) * 2);
        uint32_t* L = (uint32_t*)(sm + offL + (size_t)(r * P72 + c) * 2);
        H[0] = h0; H[1] = h1;
        L[0] = l0; L[1] = l1;
    }
}
// V: 128(kv)x64(dv) fp32 -> transposed hi/lo bf16 [dv][kv] padded tiles
__device__ __forceinline__ void load_vt(char* sm, const float* g, int tid) {
    for (int t = tid; t < 128 * 16; t += 256) {
        int kv = t >> 4, c = (t & 15) << 2;
        float4 x = *(const float4*)(g + (size_t)kv * D_ + c);
        float vv[4] = {x.x, x.y, x.z, x.w};
        #pragma unroll
        for (int j = 0; j < 4; j++) {
            __nv_bfloat16 h = __float2bfloat16_rn(vv[j]);
            __nv_bfloat16 l = __float2bfloat16_rn(vv[j] - __bfloat162float(h));
            size_t o = (size_t)((c + j) * PV + kv) * 2;
            *(__nv_bfloat16*)(sm + OVH + o) = h;
            *(__nv_bfloat16*)(sm + OVL + o) = l;
        }
    }
}

// QK^T for one 128x128 score tile; warp computes its 16-row strip.
__device__ __forceinline__ void qk_tile(uint32_t sb, int lane,
                                        const uint32_t ah[4][4],
                                        const uint32_t al[4][4],
                                        float acc[16][4]) {
    #pragma unroll
    for (int nt = 0; nt < 16; nt++) {
        #pragma unroll
        for (int i = 0; i < 4; i++) acc[nt][i] = 0.f;
        #pragma unroll
        for (int ks = 0; ks < 4; ks++) {
            uint32_t bd = sb + OKH +
                (uint32_t)(((nt * 8 + (lane & 7)) * P72 + ks * 16 +
                            ((lane >> 3) & 1) * 8) * 2);
            uint32_t bh2[2], bl2[2];
            ldsm2(bd, bh2);
            ldsm2(bd + (OKL - OKH), bl2);
            mma16816(acc[nt], ah[ks], bh2);
            mma16816(acc[nt], al[ks], bh2);
            mma16816(acc[nt], ah[ks], bl2);
        }
    }
}

__global__ __launch_bounds__(256) void attn_hmma(
    const float* __restrict__ q, const float* __restrict__ k,
    const float* __restrict__ v, float* __restrict__ out,
    float* __restrict__ attn)
{
    extern __shared__ char sm[];
    const uint32_t sb = smem_u32(sm);
    const int tid = threadIdx.x;
    const int lane = tid & 31;
    const int w = tid >> 5;
    const int m0 = w * 16;                 // warp's q-row strip within tile
    const int bh = blockIdx.y;
    const int qrow0 = blockIdx.x * TQ;
    const size_t base = (size_t)bh * S_ * D_;

    // Q tile (scaled by 1/sqrt(D)) -> smem hi/lo
    load_rm(sm, OQH, OQL, q + base + (size_t)qrow0 * D_, 0.125f, tid);
    __syncthreads();

    // A fragments for Q (constant across all k-tiles & sweeps)
    uint32_t ah[4][4], al[4][4];
    {
        int row = lane & 15;
        int colh = (lane >> 4) << 3;
        #pragma unroll
        for (int ks = 0; ks < 4; ks++) {
            uint32_t ad = sb + OQH +
                (uint32_t)(((m0 + row) * P72 + ks * 16 + colh) * 2);
            ldsm4(ad, ah[ks]);
            ldsm4(ad + (OQL - OQH), al[ks]);
        }
    }

    // ================= sweep 1: rowsums =================
    float rs0 = 0.f, rs1 = 0.f;
    for (int kt = 0; kt < NKT; kt++) {
        __syncthreads();
        load_rm(sm, OKH, OKL, k + base + (size_t)kt * TK * D_, 1.0f, tid);
        __syncthreads();
        float acc[16][4];
        qk_tile(sb, lane, ah, al, acc);
        #pragma unroll
        for (int nt = 0; nt < 16; nt++) {
            rs0 += __expf(acc[nt][0]) + __expf(acc[nt][1]);
            rs1 += __expf(acc[nt][2]) + __expf(acc[nt][3]);
        }
    }
    // reduce over the 4 lanes sharing each row
    rs0 += __shfl_xor_sync(0xFFFFFFFF, rs0, 1);
    rs0 += __shfl_xor_sync(0xFFFFFFFF, rs0, 2);
    rs1 += __shfl_xor_sync(0xFFFFFFFF, rs1, 1);
    rs1 += __shfl_xor_sync(0xFFFFFFFF, rs1, 2);
    __syncthreads();
    if ((lane & 3) == 0) {
        ((float*)(sm + ORED))[m0 + (lane >> 2)] = rs0;
        ((float*)(sm + ORED))[m0 + 8 + (lane >> 2)] = rs1;
    }
    __syncthreads();
    if (tid < 128)
        ((float*)(sm + OINV))[tid] = 1.0f / ((float*)(sm + ORED))[tid];
    __syncthreads();
    const float inv0 = ((float*)(sm + OINV))[m0 + (lane >> 2)];
    const float inv1 = ((float*)(sm + OINV))[m0 + 8 + (lane >> 2)];

    // ================= sweep 2: normalized attn + fused AV =================
    float oacc[8][4];
    #pragma unroll
    for (int d = 0; d < 8; d++)
        #pragma unroll
        for (int i = 0; i < 4; i++) oacc[d][i] = 0.f;

    for (int kt = 0; kt < NKT; kt++) {
        __syncthreads();
        load_rm(sm, OKH, OKL, k + base + (size_t)kt * TK * D_, 1.0f, tid);
        load_vt(sm, v + base + (size_t)kt * TK * D_, tid);
        __syncthreads();

        float acc[16][4];
        qk_tile(sb, lane, ah, al, acc);

        // p = exp(s) * inv  (normalized); write attn; keep p in regs
        float* arow0 = attn + ((size_t)(bh * S_ + qrow0 + m0 + (lane >> 2))) * S_
                       + kt * TK + (lane & 3) * 2;
        float* arow1 = arow0 + (size_t)8 * S_;
        #pragma unroll
        for (int nt = 0; nt < 16; nt++) {
            float p0 = __expf(acc[nt][0]) * inv0;
            float p1 = __expf(acc[nt][1]) * inv0;
            float p2 = __expf(acc[nt][2]) * inv1;
            float p3 = __expf(acc[nt][3]) * inv1;
            *(float2*)(arow0 + nt * 8) = make_float2(p0, p1);
            *(float2*)(arow1 + nt * 8) = make_float2(p2, p3);
            acc[nt][0] = p0; acc[nt][1] = p1;
            acc[nt][2] = p2; acc[nt][3] = p3;
        }

        // AV: oacc += P * V   (P A-frags come straight from score accumulators)
        #pragma unroll
        for (int kk = 0; kk < 8; kk++) {
            uint32_t aph[4], apl[4];
            split2(acc[2*kk][0],   acc[2*kk][1],   aph[0], apl[0]);
            split2(acc[2*kk][2],   acc[2*kk][3],   aph[1], apl[1]);
            split2(acc[2*kk+1][0], acc[2*kk+1][1], aph[2], apl[2]);
            split2(acc[2*kk+1][2], acc[2*kk+1][3], aph[3], apl[3]);
            #pragma unroll
            for (int dt = 0; dt < 8; dt++) {
                uint32_t vd = sb + OVH +
                    (uint32_t)(((dt * 8 + (lane & 7)) * PV + kk * 16 +
                                ((lane >> 3) & 1) * 8) * 2);
                uint32_t vh2[2], vl2[2];
                ldsm2(vd, vh2);
                ldsm2(vd + (OVL - OVH), vl2);
                mma16816(oacc[dt], aph, vh2);
                mma16816(oacc[dt], apl, vh2);
                mma16816(oacc[dt], aph, vl2);
            }
        }
    }

    // ================= epilogue: write out (already normalized) =================
    float* orow0 = out + ((size_t)(bh * S_ + qrow0 + m0 + (lane >> 2))) * D_
                   + (lane & 3) * 2;
    float* orow1 = orow0 + (size_t)8 * D_;
    #pragma unroll
    for (int dt = 0; dt < 8; dt++) {
        *(float2*)(orow0 + dt * 8) = make_float2(oacc[dt][0], oacc[dt][1]);
        *(float2*)(orow1 + dt * 8) = make_float2(oacc[dt][2], oacc[dt][3]);
    }
}

extern "C" void kernel_launch(void* const* d_in, const int* in_sizes, int n_in,
                              void* d_out, int out_size)
{
    const float* q = (const float*)d_in[0];
    const float* k = (const float*)d_in[1];
    const float* v = (const float*)d_in[2];
    float* out  = (float*)d_out;                    // [B,H,S,D]
    float* attn = out + (size_t)NBH * S_ * D_;      // [B,H,S,S]

    cudaFuncSetAttribute(attn_hmma,
                         cudaFuncAttributeMaxDynamicSharedMemorySize, SMEM_BYTES);
    dim3 g(S_ / TQ, NBH);
    attn_hmma<<<g, 256, SMEM_BYTES>>>(q, k, v, out, attn);
}

// round 6
// speedup vs baseline: 2.0489x; 1.5163x over previous
#include <cuda_runtime.h>
#include <cuda_bf16.h>
#include <cstdint>

#define S_  2048
#define D_  64
#define NBH 32
#define TQ  128
#define TK  128
#define NKT (S_/TK)
#define P72 72      // padded row stride (bf16) for Q/K tiles
#define PV  136     // padded row stride (bf16) for V^T tiles

// ---- smem byte offsets ----
#define OQH 0
#define OQL (OQH + TQ*P72*2)
#define OKH (OQL + TQ*P72*2)
#define OKL (OKH + TK*P72*2)
#define OVH (OKL + TK*P72*2)
#define OVL (OVH + D_*PV*2)
#define ORED (OVL + D_*PV*2)
#define OINV (ORED + 128*4)
#define SMEM_BYTES (OINV + 128*4)   // 109568  (2 CTAs/SM: 219136 <= 228KB)

__device__ __forceinline__ uint32_t smem_u32(const void* p) {
    uint32_t a;
    asm("{ .reg .u64 t; cvta.to.shared.u64 t, %1; cvt.u32.u64 %0, t; }"
        : "=r"(a) : "l"(p));
    return a;
}
__device__ __forceinline__ void ldsm4(uint32_t a, uint32_t r[4]) {
    asm volatile("ldmatrix.sync.aligned.m8n8.x4.shared.b16 {%0,%1,%2,%3}, [%4];"
        : "=r"(r[0]), "=r"(r[1]), "=r"(r[2]), "=r"(r[3]) : "r"(a));
}
__device__ __forceinline__ void ldsm2(uint32_t a, uint32_t r[2]) {
    asm volatile("ldmatrix.sync.aligned.m8n8.x2.shared.b16 {%0,%1}, [%2];"
        : "=r"(r[0]), "=r"(r[1]) : "r"(a));
}
__device__ __forceinline__ void mma16816(float c[4], const uint32_t a[4],
                                         const uint32_t b[2]) {
    asm volatile("mma.sync.aligned.m16n8k16.row.col.f32.bf16.bf16.f32 "
        "{%0,%1,%2,%3}, {%4,%5,%6,%7}, {%8,%9}, {%0,%1,%2,%3};"
        : "+f"(c[0]), "+f"(c[1]), "+f"(c[2]), "+f"(c[3])
        : "r"(a[0]), "r"(a[1]), "r"(a[2]), "r"(a[3]), "r"(b[0]), "r"(b[1]));
}
__device__ __forceinline__ void split2(float x, float y, uint32_t& h, uint32_t& l) {
    __nv_bfloat162 hb = __floats2bfloat162_rn(x, y);
    float lx = x - __bfloat162float(hb.x);
    float ly = y - __bfloat162float(hb.y);
    __nv_bfloat162 lb = __floats2bfloat162_rn(lx, ly);
    h = *(uint32_t*)&hb;
    l = *(uint32_t*)&lb;
}

// 128x64 fp32 gmem -> hi/lo bf16 row-major padded tiles
__device__ __forceinline__ void load_rm(char* sm, int offH, int offL,
                                        const float* g, float scale, int tid) {
    for (int t = tid; t < 128 * 16; t += 256) {
        int r = t >> 4, c = (t & 15) << 2;
        float4 x = *(const float4*)(g + (size_t)r * D_ + c);
        x.x *= scale; x.y *= scale; x.z *= scale; x.w *= scale;
        uint32_t h0, l0, h1, l1;
        split2(x.x, x.y, h0, l0);
        split2(x.z, x.w, h1, l1);
        uint32_t* H = (uint32_t*)(sm + offH + (size_t)(r * P72 + c) * 2);
        uint32_t* L = (uint32_t*)(sm + offL + (size_t)(r * P72 + c) * 2);
        H[0] = h0; H[1] = h1;
        L[0] = l0; L[1] = l1;
    }
}
// hi-only variant (sweep 1 K tiles)
__device__ __forceinline__ void load_rm_hi(char* sm, int offH,
                                           const float* g, int tid) {
    for (int t = tid; t < 128 * 16; t += 256) {
        int r = t >> 4, c = (t & 15) << 2;
        float4 x = *(const float4*)(g + (size_t)r * D_ + c);
        __nv_bfloat162 h01 = __floats2bfloat162_rn(x.x, x.y);
        __nv_bfloat162 h23 = __floats2bfloat162_rn(x.z, x.w);
        uint32_t* H = (uint32_t*)(sm + offH + (size_t)(r * P72 + c) * 2);
        H[0] = *(uint32_t*)&h01;
        H[1] = *(uint32_t*)&h23;
    }
}
// V: 128(kv)x64(dv) fp32 -> transposed hi/lo bf16 [dv][kv] padded tiles
__device__ __forceinline__ void load_vt(char* sm, const float* g, int tid) {
    for (int t = tid; t < 128 * 16; t += 256) {
        int kv = t >> 4, c = (t & 15) << 2;
        float4 x = *(const float4*)(g + (size_t)kv * D_ + c);
        float vv[4] = {x.x, x.y, x.z, x.w};
        #pragma unroll
        for (int j = 0; j < 4; j++) {
            __nv_bfloat16 h = __float2bfloat16_rn(vv[j]);
            __nv_bfloat16 l = __float2bfloat16_rn(vv[j] - __bfloat162float(h));
            size_t o = (size_t)((c + j) * PV + kv) * 2;
            *(__nv_bfloat16*)(sm + OVH + o) = h;
            *(__nv_bfloat16*)(sm + OVL + o) = l;
        }
    }
}

__global__ __launch_bounds__(256, 2) void attn_hmma(
    const float* __restrict__ q, const float* __restrict__ k,
    const float* __restrict__ v, float* __restrict__ out,
    float* __restrict__ attn)
{
    extern __shared__ char sm[];
    const uint32_t sb = smem_u32(sm);
    const int tid = threadIdx.x;
    const int lane = tid & 31;
    const int w = tid >> 5;
    const int m0 = w * 16;                 // warp's q-row strip within tile
    const int bh = blockIdx.y;
    const int qrow0 = blockIdx.x * TQ;
    const size_t base = (size_t)bh * S_ * D_;

    // hoisted ldsm fragment base addresses (per-lane constant)
    const uint32_t kfb = sb + OKH +
        (uint32_t)(((lane & 7) * P72 + ((lane >> 3) & 1) * 8) * 2);
    const uint32_t vfb = sb + OVH +
        (uint32_t)(((lane & 7) * PV + ((lane >> 3) & 1) * 8) * 2);

    // Q tile (scaled by 1/sqrt(D)) -> smem hi/lo
    load_rm(sm, OQH, OQL, q + base + (size_t)qrow0 * D_, 0.125f, tid);
    __syncthreads();

    // A fragments for Q (constant across all k-tiles & sweeps)
    uint32_t ah[4][4], al[4][4];
    {
        int row = lane & 15;
        int colh = (lane >> 4) << 3;
        #pragma unroll
        for (int ks = 0; ks < 4; ks++) {
            uint32_t ad = sb + OQH +
                (uint32_t)(((m0 + row) * P72 + ks * 16 + colh) * 2);
            ldsm4(ad, ah[ks]);
            ldsm4(ad + (OQL - OQH), al[ks]);
        }
    }

    // ================= sweep 1: rowsums (pure bf16 scores) =================
    float rs0 = 0.f, rs1 = 0.f;
    for (int kt = 0; kt < NKT; kt++) {
        __syncthreads();
        load_rm_hi(sm, OKH, k + base + (size_t)kt * TK * D_, tid);
        __syncthreads();
        #pragma unroll
        for (int nt = 0; nt < 16; nt++) {
            float a4[4] = {0.f, 0.f, 0.f, 0.f};
            #pragma unroll
            for (int ks = 0; ks < 4; ks++) {
                uint32_t b2[2];
                ldsm2(kfb + (uint32_t)((nt * 8 * P72 + ks * 16) * 2), b2);
                mma16816(a4, ah[ks], b2);
            }
            rs0 += __expf(a4[0]) + __expf(a4[1]);
            rs1 += __expf(a4[2]) + __expf(a4[3]);
        }
    }
    // reduce over the 4 lanes sharing each row
    rs0 += __shfl_xor_sync(0xFFFFFFFF, rs0, 1);
    rs0 += __shfl_xor_sync(0xFFFFFFFF, rs0, 2);
    rs1 += __shfl_xor_sync(0xFFFFFFFF, rs1, 1);
    rs1 += __shfl_xor_sync(0xFFFFFFFF, rs1, 2);
    __syncthreads();
    if ((lane & 3) == 0) {
        ((float*)(sm + ORED))[m0 + (lane >> 2)] = rs0;
        ((float*)(sm + ORED))[m0 + 8 + (lane >> 2)] = rs1;
    }
    __syncthreads();
    if (tid < 128)
        ((float*)(sm + OINV))[tid] = 1.0f / ((float*)(sm + ORED))[tid];
    __syncthreads();
    const float inv0 = ((float*)(sm + OINV))[m0 + (lane >> 2)];
    const float inv1 = ((float*)(sm + OINV))[m0 + 8 + (lane >> 2)];

    // ============ sweep 2: 3-term scores, normalized attn, fused AV ============
    float oacc[8][4];
    #pragma unroll
    for (int d = 0; d < 8; d++)
        #pragma unroll
        for (int i = 0; i < 4; i++) oacc[d][i] = 0.f;

    for (int kt = 0; kt < NKT; kt++) {
        __syncthreads();
        load_rm(sm, OKH, OKL, k + base + (size_t)kt * TK * D_, 1.0f, tid);
        load_vt(sm, v + base + (size_t)kt * TK * D_, tid);
        __syncthreads();

        float* arow0 = attn + ((size_t)(bh * S_ + qrow0 + m0 + (lane >> 2))) * S_
                       + kt * TK + (lane & 3) * 2;
        float* arow1 = arow0 + (size_t)8 * S_;

        #pragma unroll
        for (int c = 0; c < 8; c++) {      // 16 kv cols per chunk (nt = 2c, 2c+1)
            float acc2[2][4];
            #pragma unroll
            for (int i = 0; i < 4; i++) { acc2[0][i] = 0.f; acc2[1][i] = 0.f; }
            #pragma unroll
            for (int ks = 0; ks < 4; ks++) {
                uint32_t bd0 = kfb + (uint32_t)(((2*c)   * 8 * P72 + ks * 16) * 2);
                uint32_t bd1 = kfb + (uint32_t)(((2*c+1) * 8 * P72 + ks * 16) * 2);
                uint32_t b0h[2], b0l[2], b1h[2], b1l[2];
                ldsm2(bd0, b0h); ldsm2(bd0 + (OKL - OKH), b0l);
                ldsm2(bd1, b1h); ldsm2(bd1 + (OKL - OKH), b1l);
                mma16816(acc2[0], ah[ks], b0h);
                mma16816(acc2[0], al[ks], b0h);
                mma16816(acc2[0], ah[ks], b0l);
                mma16816(acc2[1], ah[ks], b1h);
                mma16816(acc2[1], al[ks], b1h);
                mma16816(acc2[1], ah[ks], b1l);
            }
            // p = exp(s)*inv, write normalized attn, keep p for AV
            float p00 = __expf(acc2[0][0]) * inv0;
            float p01 = __expf(acc2[0][1]) * inv0;
            float p02 = __expf(acc2[0][2]) * inv1;
            float p03 = __expf(acc2[0][3]) * inv1;
            float p10 = __expf(acc2[1][0]) * inv0;
            float p11 = __expf(acc2[1][1]) * inv0;
            float p12 = __expf(acc2[1][2]) * inv1;
            float p13 = __expf(acc2[1][3]) * inv1;
            *(float2*)(arow0 + c * 16)     = make_float2(p00, p01);
            *(float2*)(arow1 + c * 16)     = make_float2(p02, p03);
            *(float2*)(arow0 + c * 16 + 8) = make_float2(p10, p11);
            *(float2*)(arow1 + c * 16 + 8) = make_float2(p12, p13);

            // P A-fragments (hi/lo) for AV
            uint32_t aph[4], apl[4];
            split2(p00, p01, aph[0], apl[0]);
            split2(p02, p03, aph[1], apl[1]);
            split2(p10, p11, aph[2], apl[2]);
            split2(p12, p13, aph[3], apl[3]);

            #pragma unroll
            for (int dt = 0; dt < 8; dt++) {
                uint32_t vd = vfb + (uint32_t)((dt * 8 * PV + c * 16) * 2);
                uint32_t vh2[2], vl2[2];
                ldsm2(vd, vh2);
                ldsm2(vd + (OVL - OVH), vl2);
                mma16816(oacc[dt], aph, vh2);
                mma16816(oacc[dt], apl, vh2);
                mma16816(oacc[dt], aph, vl2);
            }
        }
    }

    // ================= epilogue: write out (already normalized) =================
    float* orow0 = out + ((size_t)(bh * S_ + qrow0 + m0 + (lane >> 2))) * D_
                   + (lane & 3) * 2;
    float* orow1 = orow0 + (size_t)8 * D_;
    #pragma unroll
    for (int dt = 0; dt < 8; dt++) {
        *(float2*)(orow0 + dt * 8) = make_float2(oacc[dt][0], oacc[dt][1]);
        *(float2*)(orow1 + dt * 8) = make_float2(oacc[dt][2], oacc[dt][3]);
    }
}

extern "C" void kernel_launch(void* const* d_in, const int* in_sizes, int n_in,
                              void* d_out, int out_size)
{
    const float* q = (const float*)d_in[0];
    const float* k = (const float*)d_in[1];
    const float* v = (const float*)d_in[2];
    float* out  = (float*)d_out;                    // [B,H,S,D]
    float* attn = out + (size_t)NBH * S_ * D_;      // [B,H,S,S]

    cudaFuncSetAttribute(attn_hmma,
                         cudaFuncAttributeMaxDynamicSharedMemorySize, SMEM_BYTES);
    dim3 g(S_ / TQ, NBH);
    attn_hmma<<<g, 256, SMEM_BYTES>>>(q, k, v, out, attn);
}

// round 7
// speedup vs baseline: 2.5447x; 1.2420x over previous
#include <cuda_runtime.h>
#include <cuda_fp16.h>
#include <cstdint>

#define S_  2048
#define D_  64
#define NBH 32
#define TQ  128
#define TK  128
#define NKT (S_/TK)
#define P72 72      // padded row stride (fp16) for Q/K tiles
#define PV  136     // padded row stride (fp16) for V^T tiles

// ---- smem byte offsets ----
#define OQ 0
#define OK (OQ + TQ*P72*2)
#define OV (OK + TK*P72*2)
#define ORED (OV + D_*PV*2)
#define OINV (ORED + 128*4)
#define SMEM_BYTES (OINV + 128*4)   // 55296  (3 CTAs/SM: 165888 <= 228KB)

__device__ __forceinline__ uint32_t smem_u32(const void* p) {
    uint32_t a;
    asm("{ .reg .u64 t; cvta.to.shared.u64 t, %1; cvt.u32.u64 %0, t; }"
        : "=r"(a) : "l"(p));
    return a;
}
__device__ __forceinline__ void ldsm4(uint32_t a, uint32_t r[4]) {
    asm volatile("ldmatrix.sync.aligned.m8n8.x4.shared.b16 {%0,%1,%2,%3}, [%4];"
        : "=r"(r[0]), "=r"(r[1]), "=r"(r[2]), "=r"(r[3]) : "r"(a));
}
__device__ __forceinline__ void mmah(float c[4], const uint32_t a[4],
                                     const uint32_t b0, const uint32_t b1) {
    asm volatile("mma.sync.aligned.m16n8k16.row.col.f32.f16.f16.f32 "
        "{%0,%1,%2,%3}, {%4,%5,%6,%7}, {%8,%9}, {%0,%1,%2,%3};"
        : "+f"(c[0]), "+f"(c[1]), "+f"(c[2]), "+f"(c[3])
        : "r"(a[0]), "r"(a[1]), "r"(a[2]), "r"(a[3]), "r"(b0), "r"(b1));
}
__device__ __forceinline__ uint32_t packh2(float x, float y) {
    __half2 h = __floats2half2_rn(x, y);
    return *(uint32_t*)&h;
}

// 128x64 fp32 gmem -> fp16 row-major padded tile
__device__ __forceinline__ void load_rm(char* sm, int off, const float* g,
                                        float scale, int tid) {
    for (int t = tid; t < 128 * 16; t += 256) {
        int r = t >> 4, c = (t & 15) << 2;
        float4 x = *(const float4*)(g + (size_t)r * D_ + c);
        uint32_t* H = (uint32_t*)(sm + off + (size_t)(r * P72 + c) * 2);
        H[0] = packh2(x.x * scale, x.y * scale);
        H[1] = packh2(x.z * scale, x.w * scale);
    }
}
// V: 128(kv)x64(dv) fp32 -> transposed fp16 [dv][kv] padded tile
__device__ __forceinline__ void load_vt(char* sm, const float* g, int tid) {
    for (int t = tid; t < 128 * 16; t += 256) {
        int kv = t >> 4, c = (t & 15) << 2;
        float4 x = *(const float4*)(g + (size_t)kv * D_ + c);
        float vv[4] = {x.x, x.y, x.z, x.w};
        #pragma unroll
        for (int j = 0; j < 4; j++)
            *(__half*)(sm + OV + (size_t)((c + j) * PV + kv) * 2) =
                __float2half_rn(vv[j]);
    }
}

__global__ __launch_bounds__(256, 3) void attn_hmma(
    const float* __restrict__ q, const float* __restrict__ k,
    const float* __restrict__ v, float* __restrict__ out,
    float* __restrict__ attn)
{
    extern __shared__ char sm[];
    const uint32_t sb = smem_u32(sm);
    const int tid = threadIdx.x;
    const int lane = tid & 31;
    const int w = tid >> 5;
    const int m0 = w * 16;                 // warp's q-row strip within tile
    const int bh = blockIdx.y;
    const int qrow0 = blockIdx.x * TQ;
    const size_t base = (size_t)bh * S_ * D_;
    const int g8 = lane >> 3;              // ldsm4 matrix index 0..3

    // hoisted ldsm4 per-lane bases
    // K: matrices = {nt0 khalf0, nt0 khalf1, nt1 khalf0, nt1 khalf1}
    const uint32_t kfb = sb + OK +
        (uint32_t)((((g8 >> 1) * 8 + (lane & 7)) * P72 + (g8 & 1) * 8) * 2);
    // V: matrices = {dt0 kvhalf0, dt0 kvhalf1, dt1 kvhalf0, dt1 kvhalf1}
    const uint32_t vfb = sb + OV +
        (uint32_t)((((g8 >> 1) * 8 + (lane & 7)) * PV + (g8 & 1) * 8) * 2);

    // Q tile (scaled by 1/sqrt(D)) -> smem fp16
    load_rm(sm, OQ, q + base + (size_t)qrow0 * D_, 0.125f, tid);
    __syncthreads();

    // A fragments for Q (constant across all k-tiles & sweeps)
    uint32_t aq[4][4];
    {
        int row = lane & 15;
        int colh = (lane >> 4) << 3;
        #pragma unroll
        for (int ks = 0; ks < 4; ks++)
            ldsm4(sb + OQ + (uint32_t)(((m0 + row) * P72 + ks * 16 + colh) * 2),
                  aq[ks]);
    }

    // ================= sweep 1: rowsums =================
    float rs0 = 0.f, rs1 = 0.f;
    for (int kt = 0; kt < NKT; kt++) {
        __syncthreads();
        load_rm(sm, OK, k + base + (size_t)kt * TK * D_, 1.0f, tid);
        __syncthreads();
        #pragma unroll
        for (int c = 0; c < 8; c++) {
            float a0[4] = {0.f,0.f,0.f,0.f}, a1[4] = {0.f,0.f,0.f,0.f};
            #pragma unroll
            for (int ks = 0; ks < 4; ks++) {
                uint32_t b[4];
                ldsm4(kfb + (uint32_t)((c * 16 * P72 + ks * 16) * 2), b);
                mmah(a0, aq[ks], b[0], b[1]);
                mmah(a1, aq[ks], b[2], b[3]);
            }
            rs0 += __expf(a0[0]) + __expf(a0[1]) + __expf(a1[0]) + __expf(a1[1]);
            rs1 += __expf(a0[2]) + __expf(a0[3]) + __expf(a1[2]) + __expf(a1[3]);
        }
    }
    rs0 += __shfl_xor_sync(0xFFFFFFFF, rs0, 1);
    rs0 += __shfl_xor_sync(0xFFFFFFFF, rs0, 2);
    rs1 += __shfl_xor_sync(0xFFFFFFFF, rs1, 1);
    rs1 += __shfl_xor_sync(0xFFFFFFFF, rs1, 2);
    __syncthreads();
    if ((lane & 3) == 0) {
        ((float*)(sm + ORED))[m0 + (lane >> 2)] = rs0;
        ((float*)(sm + ORED))[m0 + 8 + (lane >> 2)] = rs1;
    }
    __syncthreads();
    if (tid < 128)
        ((float*)(sm + OINV))[tid] = 1.0f / ((float*)(sm + ORED))[tid];
    __syncthreads();
    const float inv0 = ((float*)(sm + OINV))[m0 + (lane >> 2)];
    const float inv1 = ((float*)(sm + OINV))[m0 + 8 + (lane >> 2)];

    // ============ sweep 2: scores, normalized attn, fused AV ============
    float oacc[8][4];
    #pragma unroll
    for (int d = 0; d < 8; d++)
        #pragma unroll
        for (int i = 0; i < 4; i++) oacc[d][i] = 0.f;

    for (int kt = 0; kt < NKT; kt++) {
        __syncthreads();
        load_rm(sm, OK, k + base + (size_t)kt * TK * D_, 1.0f, tid);
        load_vt(sm, v + base + (size_t)kt * TK * D_, tid);
        __syncthreads();

        float* arow0 = attn + ((size_t)(bh * S_ + qrow0 + m0 + (lane >> 2))) * S_
                       + kt * TK + (lane & 3) * 2;
        float* arow1 = arow0 + (size_t)8 * S_;

        #pragma unroll
        for (int c = 0; c < 8; c++) {      // 16 kv cols per chunk
            float a0[4] = {0.f,0.f,0.f,0.f}, a1[4] = {0.f,0.f,0.f,0.f};
            #pragma unroll
            for (int ks = 0; ks < 4; ks++) {
                uint32_t b[4];
                ldsm4(kfb + (uint32_t)((c * 16 * P72 + ks * 16) * 2), b);
                mmah(a0, aq[ks], b[0], b[1]);
                mmah(a1, aq[ks], b[2], b[3]);
            }
            // p = exp(s)*inv, write normalized attn, keep p for AV
            float p00 = __expf(a0[0]) * inv0;
            float p01 = __expf(a0[1]) * inv0;
            float p02 = __expf(a0[2]) * inv1;
            float p03 = __expf(a0[3]) * inv1;
            float p10 = __expf(a1[0]) * inv0;
            float p11 = __expf(a1[1]) * inv0;
            float p12 = __expf(a1[2]) * inv1;
            float p13 = __expf(a1[3]) * inv1;
            *(float2*)(arow0 + c * 16)     = make_float2(p00, p01);
            *(float2*)(arow1 + c * 16)     = make_float2(p02, p03);
            *(float2*)(arow0 + c * 16 + 8) = make_float2(p10, p11);
            *(float2*)(arow1 + c * 16 + 8) = make_float2(p12, p13);

            // P A-fragment for AV
            uint32_t ap[4];
            ap[0] = packh2(p00, p01);
            ap[1] = packh2(p02, p03);
            ap[2] = packh2(p10, p11);
            ap[3] = packh2(p12, p13);

            #pragma unroll
            for (int d2 = 0; d2 < 4; d2++) {   // dv tile pairs
                uint32_t bv[4];
                ldsm4(vfb + (uint32_t)((d2 * 16 * PV + c * 16) * 2), bv);
                mmah(oacc[2*d2],     ap, bv[0], bv[1]);
                mmah(oacc[2*d2 + 1], ap, bv[2], bv[3]);
            }
        }
    }

    // ================= epilogue: write out (already normalized) =================
    float* orow0 = out + ((size_t)(bh * S_ + qrow0 + m0 + (lane >> 2))) * D_
                   + (lane & 3) * 2;
    float* orow1 = orow0 + (size_t)8 * D_;
    #pragma unroll
    for (int dt = 0; dt < 8; dt++) {
        *(float2*)(orow0 + dt * 8) = make_float2(oacc[dt][0], oacc[dt][1]);
        *(float2*)(orow1 + dt * 8) = make_float2(oacc[dt][2], oacc[dt][3]);
    }
}

extern "C" void kernel_launch(void* const* d_in, const int* in_sizes, int n_in,
                              void* d_out, int out_size)
{
    const float* q = (const float*)d_in[0];
    const float* k = (const float*)d_in[1];
    const float* v = (const float*)d_in[2];
    float* out  = (float*)d_out;                    // [B,H,S,D]
    float* attn = out + (size_t)NBH * S_ * D_;      // [B,H,S,S]

    cudaFuncSetAttribute(attn_hmma,
                         cudaFuncAttributeMaxDynamicSharedMemorySize, SMEM_BYTES);
    dim3 g(S_ / TQ, NBH);
    attn_hmma<<<g, 256, SMEM_BYTES>>>(q, k, v, out, attn);
}

// round 8
// speedup vs baseline: 4.7073x; 1.8498x over previous
#include <cuda_runtime.h>
#include <cuda_fp16.h>
#include <cstdint>

#define S_  2048
#define D_  64
#define NBH 32
#define TQ  128
#define TK  128
#define NKT (S_/TK)
#define PH  72            // padded smem row stride in halves (144B)
#define RB  144           // row stride bytes
#define TILEB 18432       // 128 * 144

// ---- smem byte offsets ----
#define KB0 0
#define KB1 18432
#define VB0 36864
#define VB1 55296         // also Q staging during prologue
#define ORED 73728
#define OINV 74240
#define SMEM_BYTES 74752  // 3 CTAs/SM: 224256 <= 228KB

// fp16 scratch (preconverted inputs; q pre-scaled by 1/sqrt(D))
#define NELEM (NBH * S_ * D_)
__device__ __half g_q16[NELEM];
__device__ __half g_k16[NELEM];
__device__ __half g_v16[NELEM];

__device__ __forceinline__ uint32_t smem_u32(const void* p) {
    uint32_t a;
    asm("{ .reg .u64 t; cvta.to.shared.u64 t, %1; cvt.u32.u64 %0, t; }"
        : "=r"(a) : "l"(p));
    return a;
}
__device__ __forceinline__ void ldsm4(uint32_t a, uint32_t r[4]) {
    asm volatile("ldmatrix.sync.aligned.m8n8.x4.shared.b16 {%0,%1,%2,%3}, [%4];"
        : "=r"(r[0]), "=r"(r[1]), "=r"(r[2]), "=r"(r[3]) : "r"(a));
}
__device__ __forceinline__ void ldsm4t(uint32_t a, uint32_t r[4]) {
    asm volatile("ldmatrix.sync.aligned.m8n8.x4.trans.shared.b16 {%0,%1,%2,%3}, [%4];"
        : "=r"(r[0]), "=r"(r[1]), "=r"(r[2]), "=r"(r[3]) : "r"(a));
}
__device__ __forceinline__ void mmah(float c[4], const uint32_t a[4],
                                     const uint32_t b0, const uint32_t b1) {
    asm volatile("mma.sync.aligned.m16n8k16.row.col.f32.f16.f16.f32 "
        "{%0,%1,%2,%3}, {%4,%5,%6,%7}, {%8,%9}, {%0,%1,%2,%3};"
        : "+f"(c[0]), "+f"(c[1]), "+f"(c[2]), "+f"(c[3])
        : "r"(a[0]), "r"(a[1]), "r"(a[2]), "r"(a[3]), "r"(b0), "r"(b1));
}
__device__ __forceinline__ uint32_t packh2(float x, float y) {
    __half2 h = __floats2half2_rn(x, y);
    return *(uint32_t*)&h;
}
#define CPA(d, s) asm volatile("cp.async.cg.shared.global [%0], [%1], 16;" \
                               :: "r"(d), "l"(s) : "memory")
#define CPC()     asm volatile("cp.async.commit_group;" ::: "memory")
#define CPW(n)    asm volatile("cp.async.wait_group %0;" :: "n"(n) : "memory")

// fetch a 128-row x 64-half tile (row-major, 128B/row) into padded smem
__device__ __forceinline__ void fetch_tile(uint32_t sdst, const __half* g, int tid) {
    #pragma unroll
    for (int i = 0; i < 4; i++) {
        int idx = i * 256 + tid;
        int row = idx >> 3, ch = idx & 7;
        CPA(sdst + (uint32_t)(row * RB + ch * 16),
            (const char*)g + (size_t)row * 128 + ch * 16);
    }
}

// ------------------- preconvert: fp32 -> fp16 -------------------
__global__ __launch_bounds__(256) void conv16(
    const float* __restrict__ q, const float* __restrict__ k,
    const float* __restrict__ v)
{
    int i = (blockIdx.x * 256 + threadIdx.x) * 4;
    const float* src; __half* dst; float sc;
    if (blockIdx.y == 0)      { src = q; dst = g_q16; sc = 0.125f; }
    else if (blockIdx.y == 1) { src = k; dst = g_k16; sc = 1.0f; }
    else                      { src = v; dst = g_v16; sc = 1.0f; }
    float4 x = *(const float4*)(src + i);
    uint2 o;
    o.x = packh2(x.x * sc, x.y * sc);
    o.y = packh2(x.z * sc, x.w * sc);
    *(uint2*)(dst + i) = o;
}

// ------------------- main attention kernel -------------------
__global__ __launch_bounds__(256, 3) void attn_hmma(
    float* __restrict__ out, float* __restrict__ attn)
{
    extern __shared__ char sm[];
    const uint32_t sb = smem_u32(sm);
    const int tid = threadIdx.x;
    const int lane = tid & 31;
    const int w = tid >> 5;
    const int m0 = w * 16;
    const int bh = blockIdx.y;
    const int qrow0 = blockIdx.x * TQ;
    const size_t base = (size_t)bh * S_ * D_;
    const int g8 = lane >> 3;

    // per-lane ldsm offsets (within a tile buffer)
    const uint32_t koff = (uint32_t)((((g8 >> 1) * 8 + (lane & 7)) * PH +
                                     (g8 & 1) * 8) * 2);
    const uint32_t voff = (uint32_t)((((lane & 7) + ((lane >> 3) & 1) * 8) * PH) * 2 +
                                     (lane >> 4) * 16);

    const __half* kg = g_k16 + base;
    const __half* vg = g_v16 + base;

    // ---- prologue: Q -> VB1, K0 -> KB0, K1 -> KB1 ----
    fetch_tile(sb + VB1, g_q16 + base + (size_t)qrow0 * D_, tid); CPC();
    fetch_tile(sb + KB0, kg, tid);                                CPC();
    fetch_tile(sb + KB1, kg + 128 * D_, tid);                     CPC();
    CPW(2);
    __syncthreads();

    // Q fragments (held for the whole kernel)
    uint32_t aq[4][4];
    {
        int row = lane & 15;
        int colh = (lane >> 4) << 3;
        #pragma unroll
        for (int ks = 0; ks < 4; ks++)
            ldsm4(sb + VB1 + (uint32_t)(((m0 + row) * PH + ks * 16 + colh) * 2),
                  aq[ks]);
    }

    // ================= sweep 1: rowsums =================
    float rs0 = 0.f, rs1 = 0.f;
    for (int kt = 0; kt < NKT; kt++) {
        CPW(1);
        __syncthreads();
        const uint32_t kb = sb + ((kt & 1) ? KB1 : KB0) + koff;
        #pragma unroll
        for (int c = 0; c < 8; c++) {
            float a0[4] = {0.f,0.f,0.f,0.f}, a1[4] = {0.f,0.f,0.f,0.f};
            #pragma unroll
            for (int ks = 0; ks < 4; ks++) {
                uint32_t b[4];
                ldsm4(kb + (uint32_t)((c * 16 * PH + ks * 16) * 2), b);
                mmah(a0, aq[ks], b[0], b[1]);
                mmah(a1, aq[ks], b[2], b[3]);
            }
            rs0 += __expf(a0[0]) + __expf(a0[1]) + __expf(a1[0]) + __expf(a1[1]);
            rs1 += __expf(a0[2]) + __expf(a0[3]) + __expf(a1[2]) + __expf(a1[3]);
        }
        __syncthreads();
        if (kt + 2 < NKT) {
            fetch_tile(sb + ((kt & 1) ? KB1 : KB0), kg + (size_t)(kt + 2) * 128 * D_, tid);
            CPC();
        }
    }
    rs0 += __shfl_xor_sync(0xFFFFFFFF, rs0, 1);
    rs0 += __shfl_xor_sync(0xFFFFFFFF, rs0, 2);
    rs1 += __shfl_xor_sync(0xFFFFFFFF, rs1, 1);
    rs1 += __shfl_xor_sync(0xFFFFFFFF, rs1, 2);
    __syncthreads();
    if ((lane & 3) == 0) {
        ((float*)(sm + ORED))[m0 + (lane >> 2)] = rs0;
        ((float*)(sm + ORED))[m0 + 8 + (lane >> 2)] = rs1;
    }
    __syncthreads();
    if (tid < 128)
        ((float*)(sm + OINV))[tid] = 1.0f / ((float*)(sm + ORED))[tid];
    __syncthreads();
    const float inv0 = ((float*)(sm + OINV))[m0 + (lane >> 2)];
    const float inv1 = ((float*)(sm + OINV))[m0 + 8 + (lane >> 2)];

    // ============ sweep 2: scores, normalized attn, fused AV ============
    float oacc[8][4];
    #pragma unroll
    for (int d = 0; d < 8; d++)
        #pragma unroll
        for (int i = 0; i < 4; i++) oacc[d][i] = 0.f;

    // prologue: (K0,V0) -> buf0, (K1,V1) -> buf1
    fetch_tile(sb + KB0, kg, tid);
    fetch_tile(sb + VB0, vg, tid);                 CPC();
    fetch_tile(sb + KB1, kg + 128 * D_, tid);
    fetch_tile(sb + VB1, vg + 128 * D_, tid);      CPC();

    for (int kt = 0; kt < NKT; kt++) {
        CPW(1);
        __syncthreads();
        const uint32_t kb = sb + ((kt & 1) ? KB1 : KB0) + koff;
        const uint32_t vb = sb + ((kt & 1) ? VB1 : VB0) + voff;

        float* arow0 = attn + ((size_t)(bh * S_ + qrow0 + m0 + (lane >> 2))) * S_
                       + kt * TK + (lane & 3) * 2;
        float* arow1 = arow0 + (size_t)8 * S_;

        #pragma unroll
        for (int c = 0; c < 8; c++) {      // 16 kv cols per chunk
            float a0[4] = {0.f,0.f,0.f,0.f}, a1[4] = {0.f,0.f,0.f,0.f};
            #pragma unroll
            for (int ks = 0; ks < 4; ks++) {
                uint32_t b[4];
                ldsm4(kb + (uint32_t)((c * 16 * PH + ks * 16) * 2), b);
                mmah(a0, aq[ks], b[0], b[1]);
                mmah(a1, aq[ks], b[2], b[3]);
            }
            float p00 = __expf(a0[0]) * inv0;
            float p01 = __expf(a0[1]) * inv0;
            float p02 = __expf(a0[2]) * inv1;
            float p03 = __expf(a0[3]) * inv1;
            float p10 = __expf(a1[0]) * inv0;
            float p11 = __expf(a1[1]) * inv0;
            float p12 = __expf(a1[2]) * inv1;
            float p13 = __expf(a1[3]) * inv1;
            *(float2*)(arow0 + c * 16)     = make_float2(p00, p01);
            *(float2*)(arow1 + c * 16)     = make_float2(p02, p03);
            *(float2*)(arow0 + c * 16 + 8) = make_float2(p10, p11);
            *(float2*)(arow1 + c * 16 + 8) = make_float2(p12, p13);

            uint32_t ap[4];
            ap[0] = packh2(p00, p01);
            ap[1] = packh2(p02, p03);
            ap[2] = packh2(p10, p11);
            ap[3] = packh2(p12, p13);

            // V via ldmatrix.trans on row-major [kv][dv] tile
            #pragma unroll
            for (int d2 = 0; d2 < 4; d2++) {
                uint32_t bv[4];
                ldsm4t(vb + (uint32_t)(c * 16 * PH * 2 + d2 * 32), bv);
                mmah(oacc[2*d2],     ap, bv[0], bv[1]);
                mmah(oacc[2*d2 + 1], ap, bv[2], bv[3]);
            }
        }
        __syncthreads();
        if (kt + 2 < NKT) {
            fetch_tile(sb + ((kt & 1) ? KB1 : KB0), kg + (size_t)(kt + 2) * 128 * D_, tid);
            fetch_tile(sb + ((kt & 1) ? VB1 : VB0), vg + (size_t)(kt + 2) * 128 * D_, tid);
            CPC();
        }
    }

    // ================= epilogue: write out (already normalized) =================
    float* orow0 = out + ((size_t)(bh * S_ + qrow0 + m0 + (lane >> 2))) * D_
                   + (lane & 3) * 2;
    float* orow1 = orow0 + (size_t)8 * D_;
    #pragma unroll
    for (int dt = 0; dt < 8; dt++) {
        *(float2*)(orow0 + dt * 8) = make_float2(oacc[dt][0], oacc[dt][1]);
        *(float2*)(orow1 + dt * 8) = make_float2(oacc[dt][2], oacc[dt][3]);
    }
}

extern "C" void kernel_launch(void* const* d_in, const int* in_sizes, int n_in,
                              void* d_out, int out_size)
{
    const float* q = (const float*)d_in[0];
    const float* k = (const float*)d_in[1];
    const float* v = (const float*)d_in[2];
    float* out  = (float*)d_out;                    // [B,H,S,D]
    float* attn = out + (size_t)NBH * S_ * D_;      // [B,H,S,S]

    dim3 gc(NELEM / (256 * 4), 3);
    conv16<<<gc, 256>>>(q, k, v);

    cudaFuncSetAttribute(attn_hmma,
                         cudaFuncAttributeMaxDynamicSharedMemorySize, SMEM_BYTES);
    dim3 g(S_ / TQ, NBH);
    attn_hmma<<<g, 256, SMEM_BYTES>>>(out, attn);
}